// round 11
// baseline (speedup 1.0000x reference)
#include <cuda_runtime.h>
#include <cuda_bf16.h>
#include <cstdint>

// ---------------------------------------------------------------------------
// MiddleLayerDecoder — round 10: R8 schedule (2-stage ring, 2 CTAs/SM,
// fused h0 in W1 GEMM) + fused (Wg0|W0a) N=512 GEMM with split epilogue.
// ---------------------------------------------------------------------------

#define N_NODES 50000
#define KPTS 8
#define M_PTS (N_NODES * KPTS)

// ---- activation planes (bf16 hi/lo) ----
__device__ __align__(16) __nv_bfloat16 g_xhi[(size_t)N_NODES * 256];
__device__ __align__(16) __nv_bfloat16 g_xlo[(size_t)N_NODES * 256];
__device__ __align__(16) __nv_bfloat16 g_h1hi[(size_t)N_NODES * 256];
__device__ __align__(16) __nv_bfloat16 g_h1lo[(size_t)N_NODES * 256];
__device__ __align__(16) __nv_bfloat16 g_h2hi[(size_t)N_NODES * 128];
__device__ __align__(16) __nv_bfloat16 g_h2lo[(size_t)N_NODES * 128];
__device__ __align__(16) __nv_bfloat16 g_fhi[(size_t)N_NODES * 64];
__device__ __align__(16) __nv_bfloat16 g_flo[(size_t)N_NODES * 64];
__device__ __align__(16) __nv_bfloat16 g_p1hi[(size_t)M_PTS * 256];
__device__ __align__(16) __nv_bfloat16 g_p1lo[(size_t)M_PTS * 256];
// fp32 scratch
__device__ float g_T[(size_t)N_NODES * 256];
__device__ float g_A[(size_t)N_NODES * 256];
// weight planes pool
__device__ __align__(16) __nv_bfloat16 g_whi[335872];
__device__ __align__(16) __nv_bfloat16 g_wlo[335872];

// pool map
#define OFF_WG0A 0        // 256 x 512 (Wg0 cols 0-255 | W0a cols 256-511)
#define OFF_WG1  131072   // 256 x 128
#define OFF_WG2  163840   // 128 x 128
#define OFF_WDEC 180224   //  64 x 128
#define OFF_W0B  188416   //  64 x 256
#define OFF_W1   204800   // 256 x 256
#define OFF_W2   270336   // 256 x 256

__device__ __forceinline__ uint32_t smem_u32(const void* p) {
    uint32_t a;
    asm("{ .reg .u64 t; cvta.to.shared.u64 t, %1; cvt.u32.u64 %0, t; }" : "=r"(a) : "l"(p));
    return a;
}
__device__ __forceinline__ uint32_t pack2(__nv_bfloat16 a, __nv_bfloat16 b) {
    return (uint32_t)__bfloat16_as_ushort(a) | ((uint32_t)__bfloat16_as_ushort(b) << 16);
}
__device__ __forceinline__ void ldm_x4(uint32_t* r, uint32_t addr) {
    asm volatile("ldmatrix.sync.aligned.m8n8.x4.shared.b16 {%0,%1,%2,%3}, [%4];"
                 : "=r"(r[0]), "=r"(r[1]), "=r"(r[2]), "=r"(r[3]) : "r"(addr));
}
__device__ __forceinline__ void ldm_x4t(uint32_t* r, uint32_t addr) {
    asm volatile("ldmatrix.sync.aligned.m8n8.x4.trans.shared.b16 {%0,%1,%2,%3}, [%4];"
                 : "=r"(r[0]), "=r"(r[1]), "=r"(r[2]), "=r"(r[3]) : "r"(addr));
}
__device__ __forceinline__ void mma16816(float* c, const uint32_t* a, const uint32_t* b) {
    asm volatile("mma.sync.aligned.m16n8k16.row.col.f32.bf16.bf16.f32 "
                 "{%0,%1,%2,%3}, {%4,%5,%6,%7}, {%8,%9}, {%0,%1,%2,%3};"
                 : "+f"(c[0]), "+f"(c[1]), "+f"(c[2]), "+f"(c[3])
                 : "r"(a[0]), "r"(a[1]), "r"(a[2]), "r"(a[3]), "r"(b[0]), "r"(b[1]));
}
__device__ __forceinline__ void cp16(uint32_t dst, const void* src, int sz) {
    asm volatile("cp.async.cg.shared.global [%0], [%1], 16, %2;"
                 :: "r"(dst), "l"(src), "r"(sz) : "memory");
}
__device__ __forceinline__ void cp_commit() {
    asm volatile("cp.async.commit_group;" ::: "memory");
}
__device__ __forceinline__ void cp_wait1() {
    asm volatile("cp.async.wait_group 1;" ::: "memory");
}

// stage layout: A planes 128x(64B,80B stride); B planes 32x(256B,272B stride)
#define ASTRIDE 80
#define BSTRIDE 272
#define SA_HI 0
#define SA_LO 10240
#define SB_HI 20480
#define SB_LO 29184
#define STAGE_BYTES 37888
#define SMEM_DYN (STAGE_BYTES * 2)

// MODE 0: A from pre-split bf16 hi/lo planes (cp.async)
// MODE 1: A = relu(Anode[p>>3] + rel[p]·W0c) computed on the fly (W1 fusion)
template <int MODE>
__global__ __launch_bounds__(256, 2)
void gemm_mma(const __nv_bfloat16* __restrict__ Ahi,
              const __nv_bfloat16* __restrict__ Alo,
              const __nv_bfloat16* __restrict__ Bhi,
              const __nv_bfloat16* __restrict__ Blo,
              const float* __restrict__ bias, const float* __restrict__ bias2,
              const float* __restrict__ Cin,
              const float* __restrict__ Anode, const float* __restrict__ rel,
              const float* __restrict__ W0c3,
              float* __restrict__ OutF,
              __nv_bfloat16* __restrict__ OutHi, __nv_bfloat16* __restrict__ OutLo,
              int M, int K, int Np, int realN, int ldc, int doRelu, int nSplit)
{
    extern __shared__ __align__(128) char smem[];
    const uint32_t sb = smem_u32(smem);
    const int tid = threadIdx.x, lane = tid & 31, wid = tid >> 5;
    const int warpM = (wid & 1) * 64;
    const int warpN = (wid >> 1) * 32;
    const long m0 = (long)blockIdx.y * 128;
    const int  n0 = blockIdx.x * 128;
    const int  nc = K >> 5;

    // cp.async: B always; A only in MODE 0
    auto issue_chunk = [&](int c) {
        const uint32_t st = sb + (uint32_t)(c & 1) * STAGE_BYTES;
        const int k0 = c << 5;
        if (MODE == 0) {
#pragma unroll
            for (int t = 0; t < 4; t++) {
                const int gi = tid + t * 256;
                const int pl = gi >> 9, idx = gi & 511;
                const int row = idx >> 2, q = idx & 3;
                const long gm = m0 + row;
                const __nv_bfloat16* src =
                    (pl ? Alo : Ahi) + (gm < M ? gm : 0) * (long)K + k0 + q * 8;
                const uint32_t dst = st + (pl ? SA_LO : SA_HI) + row * ASTRIDE + q * 16;
                cp16(dst, src, gm < M ? 16 : 0);
            }
        }
#pragma unroll
        for (int t = 0; t < 4; t++) {
            const int gi = tid + t * 256;
            const int pl = gi >> 9, idx = gi & 511;
            const int row = idx >> 4, q = idx & 15;
            const __nv_bfloat16* src =
                (pl ? Blo : Bhi) + (long)(k0 + row) * Np + n0 + q * 8;
            const uint32_t dst = st + (pl ? SB_LO : SB_HI) + row * BSTRIDE + q * 16;
            cp16(dst, src, 16);
        }
    };

    // MODE 1: per-thread row set and rel triplets (rows (tid>>3)+32t, col block tid&7)
    float r0[4], r1[4], r2[4];
    if (MODE == 1) {
#pragma unroll
        for (int t = 0; t < 4; t++) {
            const long p = m0 + (tid >> 3) + 32 * t;
            r0[t] = rel[p * 3 + 0];
            r1[t] = rel[p * 3 + 1];
            r2[t] = rel[p * 3 + 2];
        }
    }

    float acc[4][4][4];
#pragma unroll
    for (int i = 0; i < 4; i++)
#pragma unroll
        for (int j = 0; j < 4; j++)
#pragma unroll
            for (int r = 0; r < 4; r++) acc[i][j][r] = 0.f;

    const uint32_t aOff = (uint32_t)((warpM + (lane & 15)) * ASTRIDE + ((lane >> 4) << 4));
    const uint32_t bOff = (uint32_t)(((lane & 7) + ((lane >> 3) & 1) * 8) * BSTRIDE +
                                     (warpN + ((lane >> 4) << 3)) * 2);

    issue_chunk(0);
    cp_commit();

    for (int c = 0; c < nc; c++) {
        const uint32_t st = sb + (uint32_t)(c & 1) * STAGE_BYTES;

        __syncthreads();                  // MMAs of c-1 complete everywhere
        if (c + 1 < nc) issue_chunk(c + 1);
        cp_commit();

        if (MODE == 1) {
            // build A(c) = split(relu(Anode + rel·W0c)) directly in SMEM
            const int c4 = tid & 7;
            const int k0 = c << 5;
            const float4 w0 = *(const float4*)(W0c3 + 0   + k0 + c4 * 4);
            const float4 w1 = *(const float4*)(W0c3 + 256 + k0 + c4 * 4);
            const float4 w2 = *(const float4*)(W0c3 + 512 + k0 + c4 * 4);
#pragma unroll
            for (int t = 0; t < 4; t++) {
                const int row = (tid >> 3) + 32 * t;
                const long node = (m0 + row) >> 3;
                const float4 a = *(const float4*)(Anode + node * 256 + k0 + c4 * 4);
                float4 o;
                o.x = fmaxf(a.x + r0[t] * w0.x + r1[t] * w1.x + r2[t] * w2.x, 0.f);
                o.y = fmaxf(a.y + r0[t] * w0.y + r1[t] * w1.y + r2[t] * w2.y, 0.f);
                o.z = fmaxf(a.z + r0[t] * w0.z + r1[t] * w1.z + r2[t] * w2.z, 0.f);
                o.w = fmaxf(a.w + r0[t] * w0.w + r1[t] * w1.w + r2[t] * w2.w, 0.f);
                const __nv_bfloat16 hx = __float2bfloat16(o.x), hy = __float2bfloat16(o.y);
                const __nv_bfloat16 hz = __float2bfloat16(o.z), hw = __float2bfloat16(o.w);
                uint2 hp, lp;
                hp.x = pack2(hx, hy); hp.y = pack2(hz, hw);
                lp.x = pack2(__float2bfloat16(o.x - __bfloat162float(hx)),
                             __float2bfloat16(o.y - __bfloat162float(hy)));
                lp.y = pack2(__float2bfloat16(o.z - __bfloat162float(hz)),
                             __float2bfloat16(o.w - __bfloat162float(hw)));
                const int off = row * ASTRIDE + c4 * 8;
                *(uint2*)(smem + (st - sb) + SA_HI + off) = hp;
                *(uint2*)(smem + (st - sb) + SA_LO + off) = lp;
            }
        }

        cp_wait1();                       // chunk c's cp.async data arrived
        __syncthreads();                  // ...and is visible to all threads

        const uint32_t aAddr = st + aOff;
        const uint32_t bAddr = st + SB_HI + bOff;

#pragma unroll
        for (int ks = 0; ks < 2; ks++) {
            uint32_t ah[4][4], bh[8], bl[8];
#pragma unroll
            for (int mi = 0; mi < 4; mi++)
                ldm_x4(ah[mi], aAddr + SA_HI + (uint32_t)(mi * 16 * ASTRIDE + ks * 32));
#pragma unroll
            for (int j = 0; j < 2; j++) {
                const uint32_t bo = bAddr + (uint32_t)(ks * 16 * BSTRIDE + j * 32);
                ldm_x4t(bh + j * 4, bo);
                ldm_x4t(bl + j * 4, bo + (SB_LO - SB_HI));
            }
#pragma unroll
            for (int mi = 0; mi < 4; mi++)
#pragma unroll
                for (int nj = 0; nj < 4; nj++) {
                    mma16816(acc[mi][nj], ah[mi], bh + nj * 2);
                    mma16816(acc[mi][nj], ah[mi], bl + nj * 2);
                }
            uint32_t al[4][4];
#pragma unroll
            for (int mi = 0; mi < 4; mi++)
                ldm_x4(al[mi], aAddr + SA_LO + (uint32_t)(mi * 16 * ASTRIDE + ks * 32));
#pragma unroll
            for (int mi = 0; mi < 4; mi++)
#pragma unroll
                for (int nj = 0; nj < 4; nj++)
                    mma16816(acc[mi][nj], al[mi], bh + nj * 2);
        }
    }

    // ---- epilogue (nSplit: cols >= nSplit go to OutF fp32 with bias2, no relu) ----
    const long gmBase = m0 + warpM + (lane >> 2);
    const int  gcBase = n0 + warpN + (lane & 3) * 2;
#pragma unroll
    for (int mi = 0; mi < 4; mi++) {
#pragma unroll
        for (int half = 0; half < 2; half++) {
            const long gr = gmBase + mi * 16 + half * 8;
            if (gr >= M) continue;
#pragma unroll
            for (int nj = 0; nj < 4; nj++) {
                const int gc = gcBase + nj * 8;
                if (gc >= realN) continue;
                float vx = acc[mi][nj][half * 2 + 0];
                float vy = acc[mi][nj][half * 2 + 1];
                if (nSplit && gc >= nSplit) {
                    const int c2 = gc - nSplit;
                    if (bias2) { vx += bias2[c2]; vy += bias2[c2 + 1]; }
                    float2 o; o.x = vx; o.y = vy;
                    *(float2*)(OutF + gr * (long)ldc + c2) = o;
                } else {
                    if (bias) { vx += bias[gc]; vy += bias[gc + 1]; }
                    if (Cin) {
                        const float2 cv = *(const float2*)(Cin + gr * (long)ldc + gc);
                        vx += cv.x; vy += cv.y;
                    }
                    if (doRelu) { vx = fmaxf(vx, 0.f); vy = fmaxf(vy, 0.f); }
                    if (OutHi) {
                        const __nv_bfloat16 hx = __float2bfloat16(vx);
                        const __nv_bfloat16 hy = __float2bfloat16(vy);
                        *(uint32_t*)(OutHi + gr * (long)ldc + gc) = pack2(hx, hy);
                        *(uint32_t*)(OutLo + gr * (long)ldc + gc) =
                            pack2(__float2bfloat16(vx - __bfloat162float(hx)),
                                  __float2bfloat16(vy - __bfloat162float(hy)));
                    } else {
                        float2 o; o.x = vx; o.y = vy;
                        *(float2*)(OutF + gr * (long)ldc + gc) = o;
                    }
                }
            }
        }
    }
}

// ---------------------------------------------------------------------------
// weight prep: W[K,N] fp32 -> bf16 hi/lo planes at [k*NpStride + colOff + n]
// ---------------------------------------------------------------------------
__global__ __launch_bounds__(256)
void prep_weight(const float* __restrict__ W, __nv_bfloat16* __restrict__ hi,
                 __nv_bfloat16* __restrict__ lo, int K, int N,
                 int Kpad, int Nsub, int NpStride, int colOff)
{
    const int i = blockIdx.x * blockDim.x + threadIdx.x;
    if (i >= Kpad * Nsub) return;
    const int k = i / Nsub, n = i % Nsub;
    const float v = (k < K && n < N) ? W[(long)k * N + n] : 0.f;
    const __nv_bfloat16 h = __float2bfloat16(v);
    const int dst = k * NpStride + colOff + n;
    hi[dst] = h;
    lo[dst] = __float2bfloat16(v - __bfloat162float(h));
}

__global__ __launch_bounds__(256)
void split_x(const float* __restrict__ X, __nv_bfloat16* __restrict__ hi,
             __nv_bfloat16* __restrict__ lo)
{
    const long i = (long)blockIdx.x * blockDim.x + threadIdx.x;
    if (i >= (long)N_NODES * 64) return;
    const float4 v = *(const float4*)(X + i * 4);
    const __nv_bfloat16 hx = __float2bfloat16(v.x), hy = __float2bfloat16(v.y);
    const __nv_bfloat16 hz = __float2bfloat16(v.z), hw = __float2bfloat16(v.w);
    uint2 hp, lp;
    hp.x = pack2(hx, hy); hp.y = pack2(hz, hw);
    lp.x = pack2(__float2bfloat16(v.x - __bfloat162float(hx)),
                 __float2bfloat16(v.y - __bfloat162float(hy)));
    lp.y = pack2(__float2bfloat16(v.z - __bfloat162float(hz)),
                 __float2bfloat16(v.w - __bfloat162float(hw)));
    *(uint2*)(hi + i * 4) = hp;
    *(uint2*)(lo + i * 4) = lp;
}

__global__ __launch_bounds__(256)
void cluster_kernel(float* __restrict__ out)
{
    const int i = blockIdx.x * blockDim.x + threadIdx.x;
    if (i < M_PTS) out[i] = (float)(i >> 3);
}

// ---------------------------------------------------------------------------
extern "C" void kernel_launch(void* const* d_in, const int* in_sizes, int n_in,
                              void* d_out, int out_size)
{
    const float* X    = (const float*)d_in[0];
    const float* Wg0  = (const float*)d_in[1];
    const float* bg0  = (const float*)d_in[2];
    const float* Wg1  = (const float*)d_in[3];
    const float* bg1  = (const float*)d_in[4];
    const float* Wg2  = (const float*)d_in[5];
    const float* bg2  = (const float*)d_in[6];
    const float* Wdec = (const float*)d_in[7];
    const float* bdec = (const float*)d_in[8];
    const float* W0   = (const float*)d_in[9];
    const float* b0   = (const float*)d_in[10];
    const float* W1   = (const float*)d_in[11];
    const float* b1   = (const float*)d_in[12];
    const float* W2   = (const float*)d_in[13];
    const float* b2   = (const float*)d_in[14];

    float* out = (float*)d_out;
    float* out_rel     = out;
    float* out_decoded = out + 1200000;
    float* out_cluster = out + 1200000 + 102400000;

    float *T, *Abuf;
    __nv_bfloat16 *whi, *wlo, *xhi, *xlo, *h1hi, *h1lo, *h2hi, *h2lo;
    __nv_bfloat16 *fhi, *flo, *p1hi, *p1lo;
    cudaGetSymbolAddress((void**)&T,    g_T);
    cudaGetSymbolAddress((void**)&Abuf, g_A);
    cudaGetSymbolAddress((void**)&whi,  g_whi);
    cudaGetSymbolAddress((void**)&wlo,  g_wlo);
    cudaGetSymbolAddress((void**)&xhi,  g_xhi);
    cudaGetSymbolAddress((void**)&xlo,  g_xlo);
    cudaGetSymbolAddress((void**)&h1hi, g_h1hi);
    cudaGetSymbolAddress((void**)&h1lo, g_h1lo);
    cudaGetSymbolAddress((void**)&h2hi, g_h2hi);
    cudaGetSymbolAddress((void**)&h2lo, g_h2lo);
    cudaGetSymbolAddress((void**)&fhi,  g_fhi);
    cudaGetSymbolAddress((void**)&flo,  g_flo);
    cudaGetSymbolAddress((void**)&p1hi, g_p1hi);
    cudaGetSymbolAddress((void**)&p1lo, g_p1lo);

    cudaFuncSetAttribute(gemm_mma<0>, cudaFuncAttributeMaxDynamicSharedMemorySize, SMEM_DYN);
    cudaFuncSetAttribute(gemm_mma<1>, cudaFuncAttributeMaxDynamicSharedMemorySize, SMEM_DYN);

    const float* W0a = W0;
    const float* W0b = W0 + 256 * 256;
    const float* W0c = W0 + 320 * 256;

    auto prep = [&](const float* W, int off, int K, int N, int Kp, int Nsub,
                    int stride, int colOff) {
        const int total = Kp * Nsub;
        prep_weight<<<(total + 255) / 256, 256>>>(W, whi + off, wlo + off,
                                                  K, N, Kp, Nsub, stride, colOff);
    };
    prep(Wg0,  OFF_WG0A, 256, 256, 256, 256, 512, 0);    // fused cols 0-255
    prep(W0a,  OFF_WG0A, 256, 256, 256, 256, 512, 256);  // fused cols 256-511
    prep(Wg1,  OFF_WG1,  256, 128, 256, 128, 128, 0);
    prep(Wg2,  OFF_WG2,  128,  64, 128, 128, 128, 0);
    prep(Wdec, OFF_WDEC,  64,  24,  64, 128, 128, 0);
    prep(W0b,  OFF_W0B,   64, 256,  64, 256, 256, 0);
    prep(W1,   OFF_W1,   256, 256, 256, 256, 256, 0);
    prep(W2,   OFF_W2,   256, 256, 256, 256, 256, 0);

    split_x<<<(N_NODES * 64 + 255) / 256, 256>>>(X, xhi, xlo);

    auto gemm0 = [&](const __nv_bfloat16* Ahi, const __nv_bfloat16* Alo, int off,
                     const float* bias, const float* bias2, const float* Cin,
                     float* OutF, __nv_bfloat16* OutHi, __nv_bfloat16* OutLo,
                     int M, int K, int Np, int realN, int ldc, int relu, int nSplit) {
        dim3 grid((realN + 127) / 128, (M + 127) / 128);
        gemm_mma<0><<<grid, 256, SMEM_DYN>>>(Ahi, Alo, whi + off, wlo + off,
                                             bias, bias2, Cin,
                                             nullptr, nullptr, nullptr,
                                             OutF, OutHi, OutLo,
                                             M, K, Np, realN, ldc, relu, nSplit);
    };

    // fused: h1 = relu(X@Wg0+bg0) -> planes (cols 0-255); T = X@W0a+b0 -> fp32 (cols 256-511)
    gemm0(xhi, xlo, OFF_WG0A, bg0, b0, nullptr, T, h1hi, h1lo,
          N_NODES, 256, 512, 512, 256, 1, 256);
    // global MLP tail
    gemm0(h1hi, h1lo, OFF_WG1, bg1, nullptr, nullptr, nullptr, h2hi, h2lo,
          N_NODES, 256, 128, 128, 128, 1, 0);
    gemm0(h2hi, h2lo, OFF_WG2, bg2, nullptr, nullptr, nullptr, fhi, flo,
          N_NODES, 128, 128, 64, 64, 1, 0);
    // decoder head -> relative_points (fp32 into d_out)
    gemm0(fhi, flo, OFF_WDEC, bdec, nullptr, nullptr, out_rel, nullptr, nullptr,
          N_NODES, 64, 128, 24, 24, 0, 0);
    // Abuf = T + feats@W0b (fp32)
    gemm0(fhi, flo, OFF_W0B, nullptr, nullptr, T, Abuf, nullptr, nullptr,
          N_NODES, 64, 256, 256, 256, 0, 0);
    // point-MLP layer 1 with fused h0 construction (MODE 1)
    {
        dim3 grid(2, M_PTS / 128);
        gemm_mma<1><<<grid, 256, SMEM_DYN>>>(nullptr, nullptr,
                                             whi + OFF_W1, wlo + OFF_W1,
                                             b1, nullptr, nullptr,
                                             Abuf, out_rel, W0c,
                                             nullptr, p1hi, p1lo,
                                             M_PTS, 256, 256, 256, 256, 1, 0);
    }
    // point-MLP layer 2 -> decoded output (fp32)
    gemm0(p1hi, p1lo, OFF_W2, b2, nullptr, nullptr, out_decoded, nullptr, nullptr,
          M_PTS, 256, 256, 256, 256, 1, 0);
    // cluster ids
    cluster_kernel<<<(M_PTS + 255) / 256, 256>>>(out_cluster);
}

// round 12
// speedup vs baseline: 1.5304x; 1.5304x over previous
#include <cuda_runtime.h>
#include <cuda_bf16.h>
#include <cstdint>

// ---------------------------------------------------------------------------
// MiddleLayerDecoder — round 11: R8 schedule exactly; epilogue variant moved
// to a template parameter (NSPLIT) so the common GEMMs compile byte-identical
// to R8 (no register inflation); fused (Wg0|W0a) N=512 GEMM uses its own
// instantiation.
// ---------------------------------------------------------------------------

#define N_NODES 50000
#define KPTS 8
#define M_PTS (N_NODES * KPTS)

// ---- activation planes (bf16 hi/lo) ----
__device__ __align__(16) __nv_bfloat16 g_xhi[(size_t)N_NODES * 256];
__device__ __align__(16) __nv_bfloat16 g_xlo[(size_t)N_NODES * 256];
__device__ __align__(16) __nv_bfloat16 g_h1hi[(size_t)N_NODES * 256];
__device__ __align__(16) __nv_bfloat16 g_h1lo[(size_t)N_NODES * 256];
__device__ __align__(16) __nv_bfloat16 g_h2hi[(size_t)N_NODES * 128];
__device__ __align__(16) __nv_bfloat16 g_h2lo[(size_t)N_NODES * 128];
__device__ __align__(16) __nv_bfloat16 g_fhi[(size_t)N_NODES * 64];
__device__ __align__(16) __nv_bfloat16 g_flo[(size_t)N_NODES * 64];
__device__ __align__(16) __nv_bfloat16 g_p1hi[(size_t)M_PTS * 256];
__device__ __align__(16) __nv_bfloat16 g_p1lo[(size_t)M_PTS * 256];
// fp32 scratch
__device__ float g_T[(size_t)N_NODES * 256];
__device__ float g_A[(size_t)N_NODES * 256];
// weight planes pool
__device__ __align__(16) __nv_bfloat16 g_whi[335872];
__device__ __align__(16) __nv_bfloat16 g_wlo[335872];

// pool map
#define OFF_WG0A 0        // 256 x 512 (Wg0 cols 0-255 | W0a cols 256-511)
#define OFF_WG1  131072   // 256 x 128
#define OFF_WG2  163840   // 128 x 128
#define OFF_WDEC 180224   //  64 x 128
#define OFF_W0B  188416   //  64 x 256
#define OFF_W1   204800   // 256 x 256
#define OFF_W2   270336   // 256 x 256

__device__ __forceinline__ uint32_t smem_u32(const void* p) {
    uint32_t a;
    asm("{ .reg .u64 t; cvta.to.shared.u64 t, %1; cvt.u32.u64 %0, t; }" : "=r"(a) : "l"(p));
    return a;
}
__device__ __forceinline__ uint32_t pack2(__nv_bfloat16 a, __nv_bfloat16 b) {
    return (uint32_t)__bfloat16_as_ushort(a) | ((uint32_t)__bfloat16_as_ushort(b) << 16);
}
__device__ __forceinline__ void ldm_x4(uint32_t* r, uint32_t addr) {
    asm volatile("ldmatrix.sync.aligned.m8n8.x4.shared.b16 {%0,%1,%2,%3}, [%4];"
                 : "=r"(r[0]), "=r"(r[1]), "=r"(r[2]), "=r"(r[3]) : "r"(addr));
}
__device__ __forceinline__ void ldm_x4t(uint32_t* r, uint32_t addr) {
    asm volatile("ldmatrix.sync.aligned.m8n8.x4.trans.shared.b16 {%0,%1,%2,%3}, [%4];"
                 : "=r"(r[0]), "=r"(r[1]), "=r"(r[2]), "=r"(r[3]) : "r"(addr));
}
__device__ __forceinline__ void mma16816(float* c, const uint32_t* a, const uint32_t* b) {
    asm volatile("mma.sync.aligned.m16n8k16.row.col.f32.bf16.bf16.f32 "
                 "{%0,%1,%2,%3}, {%4,%5,%6,%7}, {%8,%9}, {%0,%1,%2,%3};"
                 : "+f"(c[0]), "+f"(c[1]), "+f"(c[2]), "+f"(c[3])
                 : "r"(a[0]), "r"(a[1]), "r"(a[2]), "r"(a[3]), "r"(b[0]), "r"(b[1]));
}
__device__ __forceinline__ void cp16(uint32_t dst, const void* src, int sz) {
    asm volatile("cp.async.cg.shared.global [%0], [%1], 16, %2;"
                 :: "r"(dst), "l"(src), "r"(sz) : "memory");
}
__device__ __forceinline__ void cp_commit() {
    asm volatile("cp.async.commit_group;" ::: "memory");
}
__device__ __forceinline__ void cp_wait1() {
    asm volatile("cp.async.wait_group 1;" ::: "memory");
}

// stage layout: A planes 128x(64B,80B stride); B planes 32x(256B,272B stride)
#define ASTRIDE 80
#define BSTRIDE 272
#define SA_HI 0
#define SA_LO 10240
#define SB_HI 20480
#define SB_LO 29184
#define STAGE_BYTES 37888
#define SMEM_DYN (STAGE_BYTES * 2)

// MODE 0: A from pre-split bf16 hi/lo planes (cp.async)
// MODE 1: A = relu(Anode[p>>3] + rel[p]·W0c) computed on the fly (W1 fusion)
// NSPLIT: 0 = single-output epilogue (R8-identical codegen);
//         >0 = cols >= NSPLIT go to OutF fp32 with bias2, no relu
template <int MODE, int NSPLIT>
__global__ __launch_bounds__(256, 2)
void gemm_mma(const __nv_bfloat16* __restrict__ Ahi,
              const __nv_bfloat16* __restrict__ Alo,
              const __nv_bfloat16* __restrict__ Bhi,
              const __nv_bfloat16* __restrict__ Blo,
              const float* __restrict__ bias, const float* __restrict__ bias2,
              const float* __restrict__ Cin,
              const float* __restrict__ Anode, const float* __restrict__ rel,
              const float* __restrict__ W0c3,
              float* __restrict__ OutF,
              __nv_bfloat16* __restrict__ OutHi, __nv_bfloat16* __restrict__ OutLo,
              int M, int K, int Np, int realN, int ldc, int doRelu)
{
    extern __shared__ __align__(128) char smem[];
    const uint32_t sb = smem_u32(smem);
    const int tid = threadIdx.x, lane = tid & 31, wid = tid >> 5;
    const int warpM = (wid & 1) * 64;
    const int warpN = (wid >> 1) * 32;
    const long m0 = (long)blockIdx.y * 128;
    const int  n0 = blockIdx.x * 128;
    const int  nc = K >> 5;

    // cp.async: B always; A only in MODE 0
    auto issue_chunk = [&](int c) {
        const uint32_t st = sb + (uint32_t)(c & 1) * STAGE_BYTES;
        const int k0 = c << 5;
        if (MODE == 0) {
#pragma unroll
            for (int t = 0; t < 4; t++) {
                const int gi = tid + t * 256;
                const int pl = gi >> 9, idx = gi & 511;
                const int row = idx >> 2, q = idx & 3;
                const long gm = m0 + row;
                const __nv_bfloat16* src =
                    (pl ? Alo : Ahi) + (gm < M ? gm : 0) * (long)K + k0 + q * 8;
                const uint32_t dst = st + (pl ? SA_LO : SA_HI) + row * ASTRIDE + q * 16;
                cp16(dst, src, gm < M ? 16 : 0);
            }
        }
#pragma unroll
        for (int t = 0; t < 4; t++) {
            const int gi = tid + t * 256;
            const int pl = gi >> 9, idx = gi & 511;
            const int row = idx >> 4, q = idx & 15;
            const __nv_bfloat16* src =
                (pl ? Blo : Bhi) + (long)(k0 + row) * Np + n0 + q * 8;
            const uint32_t dst = st + (pl ? SB_LO : SB_HI) + row * BSTRIDE + q * 16;
            cp16(dst, src, 16);
        }
    };

    // MODE 1: per-thread row set and rel triplets (rows (tid>>3)+32t, col block tid&7)
    float r0[4], r1[4], r2[4];
    if (MODE == 1) {
#pragma unroll
        for (int t = 0; t < 4; t++) {
            const long p = m0 + (tid >> 3) + 32 * t;
            r0[t] = rel[p * 3 + 0];
            r1[t] = rel[p * 3 + 1];
            r2[t] = rel[p * 3 + 2];
        }
    }

    float acc[4][4][4];
#pragma unroll
    for (int i = 0; i < 4; i++)
#pragma unroll
        for (int j = 0; j < 4; j++)
#pragma unroll
            for (int r = 0; r < 4; r++) acc[i][j][r] = 0.f;

    const uint32_t aOff = (uint32_t)((warpM + (lane & 15)) * ASTRIDE + ((lane >> 4) << 4));
    const uint32_t bOff = (uint32_t)(((lane & 7) + ((lane >> 3) & 1) * 8) * BSTRIDE +
                                     (warpN + ((lane >> 4) << 3)) * 2);

    issue_chunk(0);
    cp_commit();

    for (int c = 0; c < nc; c++) {
        const uint32_t st = sb + (uint32_t)(c & 1) * STAGE_BYTES;

        __syncthreads();                  // MMAs of c-1 complete everywhere
        if (c + 1 < nc) issue_chunk(c + 1);
        cp_commit();

        if (MODE == 1) {
            // build A(c) = split(relu(Anode + rel·W0c)) directly in SMEM
            const int c4 = tid & 7;
            const int k0 = c << 5;
            const float4 w0 = *(const float4*)(W0c3 + 0   + k0 + c4 * 4);
            const float4 w1 = *(const float4*)(W0c3 + 256 + k0 + c4 * 4);
            const float4 w2 = *(const float4*)(W0c3 + 512 + k0 + c4 * 4);
#pragma unroll
            for (int t = 0; t < 4; t++) {
                const int row = (tid >> 3) + 32 * t;
                const long node = (m0 + row) >> 3;
                const float4 a = *(const float4*)(Anode + node * 256 + k0 + c4 * 4);
                float4 o;
                o.x = fmaxf(a.x + r0[t] * w0.x + r1[t] * w1.x + r2[t] * w2.x, 0.f);
                o.y = fmaxf(a.y + r0[t] * w0.y + r1[t] * w1.y + r2[t] * w2.y, 0.f);
                o.z = fmaxf(a.z + r0[t] * w0.z + r1[t] * w1.z + r2[t] * w2.z, 0.f);
                o.w = fmaxf(a.w + r0[t] * w0.w + r1[t] * w1.w + r2[t] * w2.w, 0.f);
                const __nv_bfloat16 hx = __float2bfloat16(o.x), hy = __float2bfloat16(o.y);
                const __nv_bfloat16 hz = __float2bfloat16(o.z), hw = __float2bfloat16(o.w);
                uint2 hp, lp;
                hp.x = pack2(hx, hy); hp.y = pack2(hz, hw);
                lp.x = pack2(__float2bfloat16(o.x - __bfloat162float(hx)),
                             __float2bfloat16(o.y - __bfloat162float(hy)));
                lp.y = pack2(__float2bfloat16(o.z - __bfloat162float(hz)),
                             __float2bfloat16(o.w - __bfloat162float(hw)));
                const int off = row * ASTRIDE + c4 * 8;
                *(uint2*)(smem + (st - sb) + SA_HI + off) = hp;
                *(uint2*)(smem + (st - sb) + SA_LO + off) = lp;
            }
        }

        cp_wait1();                       // chunk c's cp.async data arrived
        __syncthreads();                  // ...and is visible to all threads

        const uint32_t aAddr = st + aOff;
        const uint32_t bAddr = st + SB_HI + bOff;

#pragma unroll
        for (int ks = 0; ks < 2; ks++) {
            uint32_t ah[4][4], bh[8], bl[8];
#pragma unroll
            for (int mi = 0; mi < 4; mi++)
                ldm_x4(ah[mi], aAddr + SA_HI + (uint32_t)(mi * 16 * ASTRIDE + ks * 32));
#pragma unroll
            for (int j = 0; j < 2; j++) {
                const uint32_t bo = bAddr + (uint32_t)(ks * 16 * BSTRIDE + j * 32);
                ldm_x4t(bh + j * 4, bo);
                ldm_x4t(bl + j * 4, bo + (SB_LO - SB_HI));
            }
#pragma unroll
            for (int mi = 0; mi < 4; mi++)
#pragma unroll
                for (int nj = 0; nj < 4; nj++) {
                    mma16816(acc[mi][nj], ah[mi], bh + nj * 2);
                    mma16816(acc[mi][nj], ah[mi], bl + nj * 2);
                }
            uint32_t al[4][4];
#pragma unroll
            for (int mi = 0; mi < 4; mi++)
                ldm_x4(al[mi], aAddr + SA_LO + (uint32_t)(mi * 16 * ASTRIDE + ks * 32));
#pragma unroll
            for (int mi = 0; mi < 4; mi++)
#pragma unroll
                for (int nj = 0; nj < 4; nj++)
                    mma16816(acc[mi][nj], al[mi], bh + nj * 2);
        }
    }

    // ---- epilogue ----
    const long gmBase = m0 + warpM + (lane >> 2);
    const int  gcBase = n0 + warpN + (lane & 3) * 2;
#pragma unroll
    for (int mi = 0; mi < 4; mi++) {
#pragma unroll
        for (int half = 0; half < 2; half++) {
            const long gr = gmBase + mi * 16 + half * 8;
            if (gr >= M) continue;
#pragma unroll
            for (int nj = 0; nj < 4; nj++) {
                const int gc = gcBase + nj * 8;
                if (gc >= realN) continue;
                float vx = acc[mi][nj][half * 2 + 0];
                float vy = acc[mi][nj][half * 2 + 1];
                if (NSPLIT != 0 && gc >= NSPLIT) {
                    const int c2 = gc - NSPLIT;
                    vx += bias2[c2]; vy += bias2[c2 + 1];
                    float2 o; o.x = vx; o.y = vy;
                    *(float2*)(OutF + gr * (long)ldc + c2) = o;
                } else {
                    if (bias) { vx += bias[gc]; vy += bias[gc + 1]; }
                    if (Cin) {
                        const float2 cv = *(const float2*)(Cin + gr * (long)ldc + gc);
                        vx += cv.x; vy += cv.y;
                    }
                    if (doRelu) { vx = fmaxf(vx, 0.f); vy = fmaxf(vy, 0.f); }
                    if (OutHi) {
                        const __nv_bfloat16 hx = __float2bfloat16(vx);
                        const __nv_bfloat16 hy = __float2bfloat16(vy);
                        *(uint32_t*)(OutHi + gr * (long)ldc + gc) = pack2(hx, hy);
                        *(uint32_t*)(OutLo + gr * (long)ldc + gc) =
                            pack2(__float2bfloat16(vx - __bfloat162float(hx)),
                                  __float2bfloat16(vy - __bfloat162float(hy)));
                    } else {
                        float2 o; o.x = vx; o.y = vy;
                        *(float2*)(OutF + gr * (long)ldc + gc) = o;
                    }
                }
            }
        }
    }
}

// ---------------------------------------------------------------------------
// weight prep: W[K,N] fp32 -> bf16 hi/lo planes at [k*NpStride + colOff + n]
// ---------------------------------------------------------------------------
__global__ __launch_bounds__(256)
void prep_weight(const float* __restrict__ W, __nv_bfloat16* __restrict__ hi,
                 __nv_bfloat16* __restrict__ lo, int K, int N,
                 int Kpad, int Nsub, int NpStride, int colOff)
{
    const int i = blockIdx.x * blockDim.x + threadIdx.x;
    if (i >= Kpad * Nsub) return;
    const int k = i / Nsub, n = i % Nsub;
    const float v = (k < K && n < N) ? W[(long)k * N + n] : 0.f;
    const __nv_bfloat16 h = __float2bfloat16(v);
    const int dst = k * NpStride + colOff + n;
    hi[dst] = h;
    lo[dst] = __float2bfloat16(v - __bfloat162float(h));
}

__global__ __launch_bounds__(256)
void split_x(const float* __restrict__ X, __nv_bfloat16* __restrict__ hi,
             __nv_bfloat16* __restrict__ lo)
{
    const long i = (long)blockIdx.x * blockDim.x + threadIdx.x;
    if (i >= (long)N_NODES * 64) return;
    const float4 v = *(const float4*)(X + i * 4);
    const __nv_bfloat16 hx = __float2bfloat16(v.x), hy = __float2bfloat16(v.y);
    const __nv_bfloat16 hz = __float2bfloat16(v.z), hw = __float2bfloat16(v.w);
    uint2 hp, lp;
    hp.x = pack2(hx, hy); hp.y = pack2(hz, hw);
    lp.x = pack2(__float2bfloat16(v.x - __bfloat162float(hx)),
                 __float2bfloat16(v.y - __bfloat162float(hy)));
    lp.y = pack2(__float2bfloat16(v.z - __bfloat162float(hz)),
                 __float2bfloat16(v.w - __bfloat162float(hw)));
    *(uint2*)(hi + i * 4) = hp;
    *(uint2*)(lo + i * 4) = lp;
}

__global__ __launch_bounds__(256)
void cluster_kernel(float* __restrict__ out)
{
    const int i = blockIdx.x * blockDim.x + threadIdx.x;
    if (i < M_PTS) out[i] = (float)(i >> 3);
}

// ---------------------------------------------------------------------------
extern "C" void kernel_launch(void* const* d_in, const int* in_sizes, int n_in,
                              void* d_out, int out_size)
{
    const float* X    = (const float*)d_in[0];
    const float* Wg0  = (const float*)d_in[1];
    const float* bg0  = (const float*)d_in[2];
    const float* Wg1  = (const float*)d_in[3];
    const float* bg1  = (const float*)d_in[4];
    const float* Wg2  = (const float*)d_in[5];
    const float* bg2  = (const float*)d_in[6];
    const float* Wdec = (const float*)d_in[7];
    const float* bdec = (const float*)d_in[8];
    const float* W0   = (const float*)d_in[9];
    const float* b0   = (const float*)d_in[10];
    const float* W1   = (const float*)d_in[11];
    const float* b1   = (const float*)d_in[12];
    const float* W2   = (const float*)d_in[13];
    const float* b2   = (const float*)d_in[14];

    float* out = (float*)d_out;
    float* out_rel     = out;
    float* out_decoded = out + 1200000;
    float* out_cluster = out + 1200000 + 102400000;

    float *T, *Abuf;
    __nv_bfloat16 *whi, *wlo, *xhi, *xlo, *h1hi, *h1lo, *h2hi, *h2lo;
    __nv_bfloat16 *fhi, *flo, *p1hi, *p1lo;
    cudaGetSymbolAddress((void**)&T,    g_T);
    cudaGetSymbolAddress((void**)&Abuf, g_A);
    cudaGetSymbolAddress((void**)&whi,  g_whi);
    cudaGetSymbolAddress((void**)&wlo,  g_wlo);
    cudaGetSymbolAddress((void**)&xhi,  g_xhi);
    cudaGetSymbolAddress((void**)&xlo,  g_xlo);
    cudaGetSymbolAddress((void**)&h1hi, g_h1hi);
    cudaGetSymbolAddress((void**)&h1lo, g_h1lo);
    cudaGetSymbolAddress((void**)&h2hi, g_h2hi);
    cudaGetSymbolAddress((void**)&h2lo, g_h2lo);
    cudaGetSymbolAddress((void**)&fhi,  g_fhi);
    cudaGetSymbolAddress((void**)&flo,  g_flo);
    cudaGetSymbolAddress((void**)&p1hi, g_p1hi);
    cudaGetSymbolAddress((void**)&p1lo, g_p1lo);

    cudaFuncSetAttribute((const void*)gemm_mma<0,0>,   cudaFuncAttributeMaxDynamicSharedMemorySize, SMEM_DYN);
    cudaFuncSetAttribute((const void*)gemm_mma<1,0>,   cudaFuncAttributeMaxDynamicSharedMemorySize, SMEM_DYN);
    cudaFuncSetAttribute((const void*)gemm_mma<0,256>, cudaFuncAttributeMaxDynamicSharedMemorySize, SMEM_DYN);

    const float* W0a = W0;
    const float* W0b = W0 + 256 * 256;
    const float* W0c = W0 + 320 * 256;

    auto prep = [&](const float* W, int off, int K, int N, int Kp, int Nsub,
                    int stride, int colOff) {
        const int total = Kp * Nsub;
        prep_weight<<<(total + 255) / 256, 256>>>(W, whi + off, wlo + off,
                                                  K, N, Kp, Nsub, stride, colOff);
    };
    prep(Wg0,  OFF_WG0A, 256, 256, 256, 256, 512, 0);    // fused cols 0-255
    prep(W0a,  OFF_WG0A, 256, 256, 256, 256, 512, 256);  // fused cols 256-511
    prep(Wg1,  OFF_WG1,  256, 128, 256, 128, 128, 0);
    prep(Wg2,  OFF_WG2,  128,  64, 128, 128, 128, 0);
    prep(Wdec, OFF_WDEC,  64,  24,  64, 128, 128, 0);
    prep(W0b,  OFF_W0B,   64, 256,  64, 256, 256, 0);
    prep(W1,   OFF_W1,   256, 256, 256, 256, 256, 0);
    prep(W2,   OFF_W2,   256, 256, 256, 256, 256, 0);

    split_x<<<(N_NODES * 64 + 255) / 256, 256>>>(X, xhi, xlo);

    auto gemm0 = [&](const __nv_bfloat16* Ahi, const __nv_bfloat16* Alo, int off,
                     const float* bias, const float* Cin,
                     float* OutF, __nv_bfloat16* OutHi, __nv_bfloat16* OutLo,
                     int M, int K, int Np, int realN, int ldc, int relu) {
        dim3 grid((realN + 127) / 128, (M + 127) / 128);
        gemm_mma<0,0><<<grid, 256, SMEM_DYN>>>(Ahi, Alo, whi + off, wlo + off,
                                               bias, nullptr, Cin,
                                               nullptr, nullptr, nullptr,
                                               OutF, OutHi, OutLo,
                                               M, K, Np, realN, ldc, relu);
    };

    // fused: h1 = relu(X@Wg0+bg0) -> planes (cols 0-255); T = X@W0a+b0 -> fp32 (cols 256-511)
    {
        dim3 grid(4, (N_NODES + 127) / 128);
        gemm_mma<0,256><<<grid, 256, SMEM_DYN>>>(xhi, xlo, whi + OFF_WG0A, wlo + OFF_WG0A,
                                                 bg0, b0, nullptr,
                                                 nullptr, nullptr, nullptr,
                                                 T, h1hi, h1lo,
                                                 N_NODES, 256, 512, 512, 256, 1);
    }
    // global MLP tail
    gemm0(h1hi, h1lo, OFF_WG1, bg1, nullptr, nullptr, h2hi, h2lo,
          N_NODES, 256, 128, 128, 128, 1);
    gemm0(h2hi, h2lo, OFF_WG2, bg2, nullptr, nullptr, fhi, flo,
          N_NODES, 128, 128, 64, 64, 1);
    // decoder head -> relative_points (fp32 into d_out)
    gemm0(fhi, flo, OFF_WDEC, bdec, nullptr, out_rel, nullptr, nullptr,
          N_NODES, 64, 128, 24, 24, 0);
    // Abuf = T + feats@W0b (fp32)
    gemm0(fhi, flo, OFF_W0B, nullptr, T, Abuf, nullptr, nullptr,
          N_NODES, 64, 256, 256, 256, 0);
    // point-MLP layer 1 with fused h0 construction (MODE 1)
    {
        dim3 grid(2, M_PTS / 128);
        gemm_mma<1,0><<<grid, 256, SMEM_DYN>>>(nullptr, nullptr,
                                               whi + OFF_W1, wlo + OFF_W1,
                                               b1, nullptr, nullptr,
                                               Abuf, out_rel, W0c,
                                               nullptr, p1hi, p1lo,
                                               M_PTS, 256, 256, 256, 256, 1);
    }
    // point-MLP layer 2 -> decoded output (fp32)
    gemm0(p1hi, p1lo, OFF_W2, b2, nullptr, out_decoded, nullptr, nullptr,
          M_PTS, 256, 256, 256, 256, 1);
    // cluster ids
    cluster_kernel<<<(M_PTS + 255) / 256, 256>>>(out_cluster);
}

// round 13
// speedup vs baseline: 2.0090x; 1.3127x over previous
#include <cuda_runtime.h>
#include <cuda_bf16.h>
#include <cuda_fp16.h>
#include <cstdint>

// ---------------------------------------------------------------------------
// MiddleLayerDecoder — round 12: R11 + fp16 2-term split (IS16 template arm)
// for the two dominant M=400000 GEMMs (W1 fused-h0, W2). bf16 3-term path
// untouched for all node-level GEMMs.
// ---------------------------------------------------------------------------

#define N_NODES 50000
#define KPTS 8
#define M_PTS (N_NODES * KPTS)

// ---- activation planes ----
__device__ __align__(16) __nv_bfloat16 g_xhi[(size_t)N_NODES * 256];
__device__ __align__(16) __nv_bfloat16 g_xlo[(size_t)N_NODES * 256];
__device__ __align__(16) __nv_bfloat16 g_h1hi[(size_t)N_NODES * 256];
__device__ __align__(16) __nv_bfloat16 g_h1lo[(size_t)N_NODES * 256];
__device__ __align__(16) __nv_bfloat16 g_h2hi[(size_t)N_NODES * 128];
__device__ __align__(16) __nv_bfloat16 g_h2lo[(size_t)N_NODES * 128];
__device__ __align__(16) __nv_bfloat16 g_fhi[(size_t)N_NODES * 64];
__device__ __align__(16) __nv_bfloat16 g_flo[(size_t)N_NODES * 64];
__device__ __align__(16) unsigned short g_p1hi[(size_t)M_PTS * 256];  // fp16 plane
// fp32 scratch
__device__ float g_T[(size_t)N_NODES * 256];
__device__ float g_A[(size_t)N_NODES * 256];
// weight planes pool (bf16 or fp16 bits, 2 bytes/elem)
__device__ __align__(16) unsigned short g_whi[335872];
__device__ __align__(16) unsigned short g_wlo[335872];

// pool map
#define OFF_WG0A 0        // 256 x 512 (Wg0 | W0a), bf16
#define OFF_WG1  131072   // 256 x 128, bf16
#define OFF_WG2  163840   // 128 x 128, bf16
#define OFF_WDEC 180224   //  64 x 128, bf16
#define OFF_W0B  188416   //  64 x 256, bf16
#define OFF_W1   204800   // 256 x 256, fp16
#define OFF_W2   270336   // 256 x 256, fp16

__device__ __forceinline__ uint32_t smem_u32(const void* p) {
    uint32_t a;
    asm("{ .reg .u64 t; cvta.to.shared.u64 t, %1; cvt.u32.u64 %0, t; }" : "=r"(a) : "l"(p));
    return a;
}
__device__ __forceinline__ uint32_t pack2(__nv_bfloat16 a, __nv_bfloat16 b) {
    return (uint32_t)__bfloat16_as_ushort(a) | ((uint32_t)__bfloat16_as_ushort(b) << 16);
}
__device__ __forceinline__ uint32_t pack2h(__half a, __half b) {
    return (uint32_t)__half_as_ushort(a) | ((uint32_t)__half_as_ushort(b) << 16);
}
__device__ __forceinline__ void ldm_x4(uint32_t* r, uint32_t addr) {
    asm volatile("ldmatrix.sync.aligned.m8n8.x4.shared.b16 {%0,%1,%2,%3}, [%4];"
                 : "=r"(r[0]), "=r"(r[1]), "=r"(r[2]), "=r"(r[3]) : "r"(addr));
}
__device__ __forceinline__ void ldm_x4t(uint32_t* r, uint32_t addr) {
    asm volatile("ldmatrix.sync.aligned.m8n8.x4.trans.shared.b16 {%0,%1,%2,%3}, [%4];"
                 : "=r"(r[0]), "=r"(r[1]), "=r"(r[2]), "=r"(r[3]) : "r"(addr));
}
__device__ __forceinline__ void mma16816(float* c, const uint32_t* a, const uint32_t* b) {
    asm volatile("mma.sync.aligned.m16n8k16.row.col.f32.bf16.bf16.f32 "
                 "{%0,%1,%2,%3}, {%4,%5,%6,%7}, {%8,%9}, {%0,%1,%2,%3};"
                 : "+f"(c[0]), "+f"(c[1]), "+f"(c[2]), "+f"(c[3])
                 : "r"(a[0]), "r"(a[1]), "r"(a[2]), "r"(a[3]), "r"(b[0]), "r"(b[1]));
}
__device__ __forceinline__ void mma16816h(float* c, const uint32_t* a, const uint32_t* b) {
    asm volatile("mma.sync.aligned.m16n8k16.row.col.f32.f16.f16.f32 "
                 "{%0,%1,%2,%3}, {%4,%5,%6,%7}, {%8,%9}, {%0,%1,%2,%3};"
                 : "+f"(c[0]), "+f"(c[1]), "+f"(c[2]), "+f"(c[3])
                 : "r"(a[0]), "r"(a[1]), "r"(a[2]), "r"(a[3]), "r"(b[0]), "r"(b[1]));
}
__device__ __forceinline__ void cp16(uint32_t dst, const void* src, int sz) {
    asm volatile("cp.async.cg.shared.global [%0], [%1], 16, %2;"
                 :: "r"(dst), "l"(src), "r"(sz) : "memory");
}
__device__ __forceinline__ void cp_commit() {
    asm volatile("cp.async.commit_group;" ::: "memory");
}
__device__ __forceinline__ void cp_wait1() {
    asm volatile("cp.async.wait_group 1;" ::: "memory");
}

// stage layouts
#define ASTRIDE 80
#define BSTRIDE 272
#define SA_HI 0
// bf16 (3-term): A hi/lo + B hi/lo
#define SA_LO_B 10240
#define SB_HI_B 20480
#define STAGE_B 37888
// fp16 (2-term): A hi only + B hi/lo
#define SB_HI_H 10240
#define STAGE_H 27648
#define SB_LO_DELTA 8704   // 32*272, same for both layouts
#define SMEM_DYN_B (STAGE_B * 2)
#define SMEM_DYN_H (STAGE_H * 2)

// MODE 0: A from pre-split planes (cp.async); MODE 1: A built on the fly (h0)
// NSPLIT>0: cols >= NSPLIT -> OutF fp32 + bias2, no relu
// IS16: fp16 2-term (A single plane) instead of bf16 3-term
template <int MODE, int NSPLIT, int IS16>
__global__ __launch_bounds__(256, 2)
void gemm_mma(const unsigned short* __restrict__ Ahi,
              const unsigned short* __restrict__ Alo,
              const unsigned short* __restrict__ Bhi,
              const unsigned short* __restrict__ Blo,
              const float* __restrict__ bias, const float* __restrict__ bias2,
              const float* __restrict__ Cin,
              const float* __restrict__ Anode, const float* __restrict__ rel,
              const float* __restrict__ W0c3,
              float* __restrict__ OutF,
              unsigned short* __restrict__ OutHi, unsigned short* __restrict__ OutLo,
              int M, int K, int Np, int realN, int ldc, int doRelu)
{
    constexpr uint32_t SBH = IS16 ? SB_HI_H : SB_HI_B;
    constexpr uint32_t STB = IS16 ? STAGE_H : STAGE_B;

    extern __shared__ __align__(128) char smem[];
    const uint32_t sb = smem_u32(smem);
    const int tid = threadIdx.x, lane = tid & 31, wid = tid >> 5;
    const int warpM = (wid & 1) * 64;
    const int warpN = (wid >> 1) * 32;
    const long m0 = (long)blockIdx.y * 128;
    const int  n0 = blockIdx.x * 128;
    const int  nc = K >> 5;

    auto issue_chunk = [&](int c) {
        const uint32_t st = sb + (uint32_t)(c & 1) * STB;
        const int k0 = c << 5;
        if (MODE == 0) {
            // A granules: hi plane (and lo plane if 3-term)
#pragma unroll
            for (int t = 0; t < (IS16 ? 2 : 4); t++) {
                const int gi = tid + t * 256;
                const int pl = gi >> 9, idx = gi & 511;
                const int row = idx >> 2, q = idx & 3;
                const long gm = m0 + row;
                const unsigned short* src =
                    (pl ? Alo : Ahi) + (gm < M ? gm : 0) * (long)K + k0 + q * 8;
                const uint32_t dst = st + (pl ? SA_LO_B : SA_HI) + row * ASTRIDE + q * 16;
                cp16(dst, src, gm < M ? 16 : 0);
            }
        }
#pragma unroll
        for (int t = 0; t < 4; t++) {
            const int gi = tid + t * 256;
            const int pl = gi >> 9, idx = gi & 511;
            const int row = idx >> 4, q = idx & 15;
            const unsigned short* src =
                (pl ? Blo : Bhi) + (long)(k0 + row) * Np + n0 + q * 8;
            const uint32_t dst = st + SBH + (pl ? SB_LO_DELTA : 0) + row * BSTRIDE + q * 16;
            cp16(dst, src, 16);
        }
    };

    float r0[4], r1[4], r2[4];
    if (MODE == 1) {
#pragma unroll
        for (int t = 0; t < 4; t++) {
            const long p = m0 + (tid >> 3) + 32 * t;
            r0[t] = rel[p * 3 + 0];
            r1[t] = rel[p * 3 + 1];
            r2[t] = rel[p * 3 + 2];
        }
    }

    float acc[4][4][4];
#pragma unroll
    for (int i = 0; i < 4; i++)
#pragma unroll
        for (int j = 0; j < 4; j++)
#pragma unroll
            for (int r = 0; r < 4; r++) acc[i][j][r] = 0.f;

    const uint32_t aOff = (uint32_t)((warpM + (lane & 15)) * ASTRIDE + ((lane >> 4) << 4));
    const uint32_t bOff = (uint32_t)(((lane & 7) + ((lane >> 3) & 1) * 8) * BSTRIDE +
                                     (warpN + ((lane >> 4) << 3)) * 2);

    issue_chunk(0);
    cp_commit();

    for (int c = 0; c < nc; c++) {
        const uint32_t st = sb + (uint32_t)(c & 1) * STB;

        __syncthreads();
        if (c + 1 < nc) issue_chunk(c + 1);
        cp_commit();

        if (MODE == 1) {
            // build A(c) = cvt(relu(Anode + rel·W0c)) directly in SMEM
            const int c4 = tid & 7;
            const int k0 = c << 5;
            const float4 w0 = *(const float4*)(W0c3 + 0   + k0 + c4 * 4);
            const float4 w1 = *(const float4*)(W0c3 + 256 + k0 + c4 * 4);
            const float4 w2 = *(const float4*)(W0c3 + 512 + k0 + c4 * 4);
#pragma unroll
            for (int t = 0; t < 4; t++) {
                const int row = (tid >> 3) + 32 * t;
                const long node = (m0 + row) >> 3;
                const float4 a = *(const float4*)(Anode + node * 256 + k0 + c4 * 4);
                float4 o;
                o.x = fmaxf(a.x + r0[t] * w0.x + r1[t] * w1.x + r2[t] * w2.x, 0.f);
                o.y = fmaxf(a.y + r0[t] * w0.y + r1[t] * w1.y + r2[t] * w2.y, 0.f);
                o.z = fmaxf(a.z + r0[t] * w0.z + r1[t] * w1.z + r2[t] * w2.z, 0.f);
                o.w = fmaxf(a.w + r0[t] * w0.w + r1[t] * w1.w + r2[t] * w2.w, 0.f);
                const int off = row * ASTRIDE + c4 * 8;
                if (IS16) {
                    uint2 hp;
                    hp.x = pack2h(__float2half_rn(o.x), __float2half_rn(o.y));
                    hp.y = pack2h(__float2half_rn(o.z), __float2half_rn(o.w));
                    *(uint2*)(smem + (st - sb) + SA_HI + off) = hp;
                } else {
                    const __nv_bfloat16 hx = __float2bfloat16(o.x), hy = __float2bfloat16(o.y);
                    const __nv_bfloat16 hz = __float2bfloat16(o.z), hw = __float2bfloat16(o.w);
                    uint2 hp, lp;
                    hp.x = pack2(hx, hy); hp.y = pack2(hz, hw);
                    lp.x = pack2(__float2bfloat16(o.x - __bfloat162float(hx)),
                                 __float2bfloat16(o.y - __bfloat162float(hy)));
                    lp.y = pack2(__float2bfloat16(o.z - __bfloat162float(hz)),
                                 __float2bfloat16(o.w - __bfloat162float(hw)));
                    *(uint2*)(smem + (st - sb) + SA_HI + off) = hp;
                    *(uint2*)(smem + (st - sb) + SA_LO_B + off) = lp;
                }
            }
        }

        cp_wait1();
        __syncthreads();

        const uint32_t aAddr = st + aOff;
        const uint32_t bAddr = st + SBH + bOff;

#pragma unroll
        for (int ks = 0; ks < 2; ks++) {
            uint32_t ah[4][4], bh[8], bl[8];
#pragma unroll
            for (int mi = 0; mi < 4; mi++)
                ldm_x4(ah[mi], aAddr + SA_HI + (uint32_t)(mi * 16 * ASTRIDE + ks * 32));
#pragma unroll
            for (int j = 0; j < 2; j++) {
                const uint32_t bo = bAddr + (uint32_t)(ks * 16 * BSTRIDE + j * 32);
                ldm_x4t(bh + j * 4, bo);
                ldm_x4t(bl + j * 4, bo + SB_LO_DELTA);
            }
#pragma unroll
            for (int mi = 0; mi < 4; mi++)
#pragma unroll
                for (int nj = 0; nj < 4; nj++) {
                    if (IS16) {
                        mma16816h(acc[mi][nj], ah[mi], bh + nj * 2);
                        mma16816h(acc[mi][nj], ah[mi], bl + nj * 2);
                    } else {
                        mma16816(acc[mi][nj], ah[mi], bh + nj * 2);
                        mma16816(acc[mi][nj], ah[mi], bl + nj * 2);
                    }
                }
            if (!IS16) {
                uint32_t al[4][4];
#pragma unroll
                for (int mi = 0; mi < 4; mi++)
                    ldm_x4(al[mi], aAddr + SA_LO_B + (uint32_t)(mi * 16 * ASTRIDE + ks * 32));
#pragma unroll
                for (int mi = 0; mi < 4; mi++)
#pragma unroll
                    for (int nj = 0; nj < 4; nj++)
                        mma16816(acc[mi][nj], al[mi], bh + nj * 2);
            }
        }
    }

    // ---- epilogue ----
    const long gmBase = m0 + warpM + (lane >> 2);
    const int  gcBase = n0 + warpN + (lane & 3) * 2;
#pragma unroll
    for (int mi = 0; mi < 4; mi++) {
#pragma unroll
        for (int half = 0; half < 2; half++) {
            const long gr = gmBase + mi * 16 + half * 8;
            if (gr >= M) continue;
#pragma unroll
            for (int nj = 0; nj < 4; nj++) {
                const int gc = gcBase + nj * 8;
                if (gc >= realN) continue;
                float vx = acc[mi][nj][half * 2 + 0];
                float vy = acc[mi][nj][half * 2 + 1];
                if (NSPLIT != 0 && gc >= NSPLIT) {
                    const int c2 = gc - NSPLIT;
                    vx += bias2[c2]; vy += bias2[c2 + 1];
                    float2 o; o.x = vx; o.y = vy;
                    *(float2*)(OutF + gr * (long)ldc + c2) = o;
                } else {
                    if (bias) { vx += bias[gc]; vy += bias[gc + 1]; }
                    if (Cin) {
                        const float2 cv = *(const float2*)(Cin + gr * (long)ldc + gc);
                        vx += cv.x; vy += cv.y;
                    }
                    if (doRelu) { vx = fmaxf(vx, 0.f); vy = fmaxf(vy, 0.f); }
                    if (OutHi) {
                        if (IS16) {
                            *(uint32_t*)(OutHi + gr * (long)ldc + gc) =
                                pack2h(__float2half_rn(vx), __float2half_rn(vy));
                        } else {
                            const __nv_bfloat16 hx = __float2bfloat16(vx);
                            const __nv_bfloat16 hy = __float2bfloat16(vy);
                            *(uint32_t*)(OutHi + gr * (long)ldc + gc) = pack2(hx, hy);
                            *(uint32_t*)(OutLo + gr * (long)ldc + gc) =
                                pack2(__float2bfloat16(vx - __bfloat162float(hx)),
                                      __float2bfloat16(vy - __bfloat162float(hy)));
                        }
                    } else {
                        float2 o; o.x = vx; o.y = vy;
                        *(float2*)(OutF + gr * (long)ldc + gc) = o;
                    }
                }
            }
        }
    }
}

// ---------------------------------------------------------------------------
// weight prep (bf16 planes)
__global__ __launch_bounds__(256)
void prep_weight(const float* __restrict__ W, unsigned short* __restrict__ hi,
                 unsigned short* __restrict__ lo, int K, int N,
                 int Kpad, int Nsub, int NpStride, int colOff)
{
    const int i = blockIdx.x * blockDim.x + threadIdx.x;
    if (i >= Kpad * Nsub) return;
    const int k = i / Nsub, n = i % Nsub;
    const float v = (k < K && n < N) ? W[(long)k * N + n] : 0.f;
    const __nv_bfloat16 h = __float2bfloat16(v);
    const int dst = k * NpStride + colOff + n;
    hi[dst] = __bfloat16_as_ushort(h);
    lo[dst] = __bfloat16_as_ushort(__float2bfloat16(v - __bfloat162float(h)));
}

// weight prep (fp16 planes)
__global__ __launch_bounds__(256)
void prep_weight_h(const float* __restrict__ W, unsigned short* __restrict__ hi,
                   unsigned short* __restrict__ lo, int K, int N,
                   int Kpad, int Nsub, int NpStride, int colOff)
{
    const int i = blockIdx.x * blockDim.x + threadIdx.x;
    if (i >= Kpad * Nsub) return;
    const int k = i / Nsub, n = i % Nsub;
    const float v = (k < K && n < N) ? W[(long)k * N + n] : 0.f;
    const __half h = __float2half_rn(v);
    const int dst = k * NpStride + colOff + n;
    hi[dst] = __half_as_ushort(h);
    lo[dst] = __half_as_ushort(__float2half_rn(v - __half2float(h)));
}

__global__ __launch_bounds__(256)
void split_x(const float* __restrict__ X, unsigned short* __restrict__ hi,
             unsigned short* __restrict__ lo)
{
    const long i = (long)blockIdx.x * blockDim.x + threadIdx.x;
    if (i >= (long)N_NODES * 64) return;
    const float4 v = *(const float4*)(X + i * 4);
    const __nv_bfloat16 hx = __float2bfloat16(v.x), hy = __float2bfloat16(v.y);
    const __nv_bfloat16 hz = __float2bfloat16(v.z), hw = __float2bfloat16(v.w);
    uint2 hp, lp;
    hp.x = pack2(hx, hy); hp.y = pack2(hz, hw);
    lp.x = pack2(__float2bfloat16(v.x - __bfloat162float(hx)),
                 __float2bfloat16(v.y - __bfloat162float(hy)));
    lp.y = pack2(__float2bfloat16(v.z - __bfloat162float(hz)),
                 __float2bfloat16(v.w - __bfloat162float(hw)));
    *(uint2*)(hi + i * 4) = hp;
    *(uint2*)(lo + i * 4) = lp;
}

__global__ __launch_bounds__(256)
void cluster_kernel(float* __restrict__ out)
{
    const int i = blockIdx.x * blockDim.x + threadIdx.x;
    if (i < M_PTS) out[i] = (float)(i >> 3);
}

// ---------------------------------------------------------------------------
extern "C" void kernel_launch(void* const* d_in, const int* in_sizes, int n_in,
                              void* d_out, int out_size)
{
    const float* X    = (const float*)d_in[0];
    const float* Wg0  = (const float*)d_in[1];
    const float* bg0  = (const float*)d_in[2];
    const float* Wg1  = (const float*)d_in[3];
    const float* bg1  = (const float*)d_in[4];
    const float* Wg2  = (const float*)d_in[5];
    const float* bg2  = (const float*)d_in[6];
    const float* Wdec = (const float*)d_in[7];
    const float* bdec = (const float*)d_in[8];
    const float* W0   = (const float*)d_in[9];
    const float* b0   = (const float*)d_in[10];
    const float* W1   = (const float*)d_in[11];
    const float* b1   = (const float*)d_in[12];
    const float* W2   = (const float*)d_in[13];
    const float* b2   = (const float*)d_in[14];

    float* out = (float*)d_out;
    float* out_rel     = out;
    float* out_decoded = out + 1200000;
    float* out_cluster = out + 1200000 + 102400000;

    float *T, *Abuf;
    unsigned short *whi, *wlo, *xhi, *xlo, *h1hi, *h1lo, *h2hi, *h2lo;
    unsigned short *fhi, *flo, *p1hi;
    cudaGetSymbolAddress((void**)&T,    g_T);
    cudaGetSymbolAddress((void**)&Abuf, g_A);
    cudaGetSymbolAddress((void**)&whi,  g_whi);
    cudaGetSymbolAddress((void**)&wlo,  g_wlo);
    cudaGetSymbolAddress((void**)&xhi,  g_xhi);
    cudaGetSymbolAddress((void**)&xlo,  g_xlo);
    cudaGetSymbolAddress((void**)&h1hi, g_h1hi);
    cudaGetSymbolAddress((void**)&h1lo, g_h1lo);
    cudaGetSymbolAddress((void**)&h2hi, g_h2hi);
    cudaGetSymbolAddress((void**)&h2lo, g_h2lo);
    cudaGetSymbolAddress((void**)&fhi,  g_fhi);
    cudaGetSymbolAddress((void**)&flo,  g_flo);
    cudaGetSymbolAddress((void**)&p1hi, g_p1hi);

    cudaFuncSetAttribute((const void*)gemm_mma<0,0,0>,   cudaFuncAttributeMaxDynamicSharedMemorySize, SMEM_DYN_B);
    cudaFuncSetAttribute((const void*)gemm_mma<0,256,0>, cudaFuncAttributeMaxDynamicSharedMemorySize, SMEM_DYN_B);
    cudaFuncSetAttribute((const void*)gemm_mma<1,0,1>,   cudaFuncAttributeMaxDynamicSharedMemorySize, SMEM_DYN_H);
    cudaFuncSetAttribute((const void*)gemm_mma<0,0,1>,   cudaFuncAttributeMaxDynamicSharedMemorySize, SMEM_DYN_H);

    const float* W0a = W0;
    const float* W0b = W0 + 256 * 256;
    const float* W0c = W0 + 320 * 256;

    auto prep = [&](const float* W, int off, int K, int N, int Kp, int Nsub,
                    int stride, int colOff) {
        const int total = Kp * Nsub;
        prep_weight<<<(total + 255) / 256, 256>>>(W, whi + off, wlo + off,
                                                  K, N, Kp, Nsub, stride, colOff);
    };
    prep(Wg0,  OFF_WG0A, 256, 256, 256, 256, 512, 0);
    prep(W0a,  OFF_WG0A, 256, 256, 256, 256, 512, 256);
    prep(Wg1,  OFF_WG1,  256, 128, 256, 128, 128, 0);
    prep(Wg2,  OFF_WG2,  128,  64, 128, 128, 128, 0);
    prep(Wdec, OFF_WDEC,  64,  24,  64, 128, 128, 0);
    prep(W0b,  OFF_W0B,   64, 256,  64, 256, 256, 0);
    // fp16 planes for the two big GEMMs
    prep_weight_h<<<(256 * 256 + 255) / 256, 256>>>(W1, whi + OFF_W1, wlo + OFF_W1,
                                                    256, 256, 256, 256, 256, 0);
    prep_weight_h<<<(256 * 256 + 255) / 256, 256>>>(W2, whi + OFF_W2, wlo + OFF_W2,
                                                    256, 256, 256, 256, 256, 0);

    split_x<<<(N_NODES * 64 + 255) / 256, 256>>>(X, xhi, xlo);

    auto gemm0 = [&](const unsigned short* Ahi, const unsigned short* Alo, int off,
                     const float* bias, const float* Cin,
                     float* OutF, unsigned short* OutHi, unsigned short* OutLo,
                     int M, int K, int Np, int realN, int ldc, int relu) {
        dim3 grid((realN + 127) / 128, (M + 127) / 128);
        gemm_mma<0,0,0><<<grid, 256, SMEM_DYN_B>>>(Ahi, Alo, whi + off, wlo + off,
                                                   bias, nullptr, Cin,
                                                   nullptr, nullptr, nullptr,
                                                   OutF, OutHi, OutLo,
                                                   M, K, Np, realN, ldc, relu);
    };

    // fused: h1 = relu(X@Wg0+bg0) (cols 0-255, planes); T = X@W0a+b0 (cols 256-511, fp32)
    {
        dim3 grid(4, (N_NODES + 127) / 128);
        gemm_mma<0,256,0><<<grid, 256, SMEM_DYN_B>>>(xhi, xlo, whi + OFF_WG0A, wlo + OFF_WG0A,
                                                     bg0, b0, nullptr,
                                                     nullptr, nullptr, nullptr,
                                                     T, h1hi, h1lo,
                                                     N_NODES, 256, 512, 512, 256, 1);
    }
    // global MLP tail
    gemm0(h1hi, h1lo, OFF_WG1, bg1, nullptr, nullptr, h2hi, h2lo,
          N_NODES, 256, 128, 128, 128, 1);
    gemm0(h2hi, h2lo, OFF_WG2, bg2, nullptr, nullptr, fhi, flo,
          N_NODES, 128, 128, 64, 64, 1);
    // decoder head -> relative_points (fp32 into d_out)
    gemm0(fhi, flo, OFF_WDEC, bdec, nullptr, out_rel, nullptr, nullptr,
          N_NODES, 64, 128, 24, 24, 0);
    // Abuf = T + feats@W0b (fp32)
    gemm0(fhi, flo, OFF_W0B, nullptr, T, Abuf, nullptr, nullptr,
          N_NODES, 64, 256, 256, 256, 0);
    // point-MLP layer 1: fused h0 build, fp16 2-term -> p1 fp16 plane
    {
        dim3 grid(2, M_PTS / 128);
        gemm_mma<1,0,1><<<grid, 256, SMEM_DYN_H>>>(nullptr, nullptr,
                                                   whi + OFF_W1, wlo + OFF_W1,
                                                   b1, nullptr, nullptr,
                                                   Abuf, out_rel, W0c,
                                                   nullptr, p1hi, nullptr,
                                                   M_PTS, 256, 256, 256, 256, 1);
    }
    // point-MLP layer 2: fp16 2-term -> decoded output (fp32)
    {
        dim3 grid(2, M_PTS / 128);
        gemm_mma<0,0,1><<<grid, 256, SMEM_DYN_H>>>(p1hi, nullptr,
                                                   whi + OFF_W2, wlo + OFF_W2,
                                                   b2, nullptr, nullptr,
                                                   nullptr, nullptr, nullptr,
                                                   out_decoded, nullptr, nullptr,
                                                   M_PTS, 256, 256, 256, 256, 1);
    }
    // cluster ids
    cluster_kernel<<<(M_PTS + 255) / 256, 256>>>(out_cluster);
}